// round 10
// baseline (speedup 1.0000x reference)
#include <cuda_runtime.h>
#include <math.h>
#include <stdint.h>

#define BATCH 2
#define SEQ   2048
#define EMB   1024
#define NH    16
#define HD    64
#define QKV3  3072
#define MROWS 4096

// Scratch (allocation-free: __device__ globals)
__device__ float    g_qkv[(size_t)MROWS * QKV3];  // tf32 bits after QKV gemm (+rope)
__device__ float    g_att[(size_t)MROWS * EMB];   // tf32 bits after attention
__device__ unsigned g_xt [(size_t)MROWS * EMB];   // x as tf32 bits
__device__ unsigned g_wqt[(size_t)EMB * QKV3];    // W_qkv tf32 bits
__device__ unsigned g_wot[(size_t)EMB * EMB];     // W_out tf32 bits

// ---------------------------------------------------------------------------
__device__ __forceinline__ unsigned f2tf(float x) {
    unsigned u;
    asm("cvt.rna.tf32.f32 %0, %1;" : "=r"(u) : "f"(x));
    return u;
}
__device__ __forceinline__ void mma8(float* c, const unsigned* a, const unsigned* b) {
    asm volatile(
        "mma.sync.aligned.m16n8k8.row.col.f32.tf32.tf32.f32 "
        "{%0,%1,%2,%3}, {%4,%5,%6,%7}, {%8,%9}, {%0,%1,%2,%3};"
        : "+f"(c[0]), "+f"(c[1]), "+f"(c[2]), "+f"(c[3])
        : "r"(a[0]), "r"(a[1]), "r"(a[2]), "r"(a[3]), "r"(b[0]), "r"(b[1]));
}
__device__ __forceinline__ void cp16(unsigned* smem_dst, const void* gptr) {
    unsigned sa = (unsigned)__cvta_generic_to_shared(smem_dst);
    asm volatile("cp.async.cg.shared.global [%0], [%1], 16;" :: "r"(sa), "l"(gptr));
}

// ---------------------------------------------------------------------------
// Pre-pass: fp32 -> tf32 bit patterns, vectorized.
// ---------------------------------------------------------------------------
__global__ __launch_bounds__(256) void cvt_tf32_kernel(
    const float4* __restrict__ src, uint4* __restrict__ dst, int n4)
{
    int i = blockIdx.x * 256 + threadIdx.x;
    if (i < n4) {
        float4 v = src[i];
        dst[i] = make_uint4(f2tf(v.x), f2tf(v.y), f2tf(v.z), f2tf(v.w));
    }
}

// ---------------------------------------------------------------------------
// tf32 mma.sync GEMM, cp.async double-buffered (round-8, passing).
// C[M,N] = A[M,K] @ B[K,N]; A,B tf32 bits. BM=BN=128, BK=32, 8 warps.
// ROPE=1: rotary + tf32-bit store (QKV). ROPE=0: fp32 store (out-proj).
// ---------------------------------------------------------------------------
#define AS_STG  4608   // 128*36 words per stage
#define BS_STG  4352   // 32*136 words per stage
#define BS_BASE 9216   // 2*AS_STG
#define GEMM_SMEM_BYTES ((2 * AS_STG + 2 * BS_STG) * 4)

template <int ROPE>
__global__ __launch_bounds__(256, 2) void gemm_tc(
    const unsigned* __restrict__ A, const unsigned* __restrict__ B,
    float* __restrict__ C, int M, int N, int K)
{
    extern __shared__ unsigned sm[];

    const int tid  = threadIdx.x;
    const int lane = tid & 31;
    const int warp = tid >> 5;
    const int g    = lane >> 2;
    const int tg   = lane & 3;
    const int wm   = warp >> 1;
    const int wn   = warp & 1;
    const int bm   = blockIdx.y * 128;
    const int bn   = blockIdx.x * 128;
    const int nt   = K >> 5;

    auto issue = [&](int kt, int s) {
        const int k0 = kt * 32;
        #pragma unroll
        for (int t = 0; t < 4; t++) {
            int ch = tid + t * 256;
            int ar = ch >> 3, ac = (ch & 7) * 4;
            cp16(sm + s * AS_STG + ar * 36 + ac,
                 A + (size_t)(bm + ar) * K + k0 + ac);
            int br = ch >> 5, bc = (ch & 31) * 4;
            cp16(sm + BS_BASE + s * BS_STG + br * 136 + bc,
                 B + (size_t)(k0 + br) * N + bn + bc);
        }
        asm volatile("cp.async.commit_group;");
    };

    float acc[2][8][4];
    #pragma unroll
    for (int mf = 0; mf < 2; mf++)
        #pragma unroll
        for (int nf = 0; nf < 8; nf++)
            #pragma unroll
            for (int i = 0; i < 4; i++) acc[mf][nf][i] = 0.0f;

    issue(0, 0);
    issue(1, 1);

    for (int kt = 0; kt < nt; kt++) {
        asm volatile("cp.async.wait_group 1;" ::: "memory");
        __syncthreads();
        const unsigned* As = sm + (kt & 1) * AS_STG;
        const unsigned* Bs = sm + BS_BASE + (kt & 1) * BS_STG;

        #pragma unroll
        for (int ks = 0; ks < 4; ks++) {
            unsigned a[2][4];
            #pragma unroll
            for (int mf = 0; mf < 2; mf++) {
                int r = wm * 32 + mf * 16;
                a[mf][0] = As[(r + g    ) * 36 + ks * 8 + tg];
                a[mf][1] = As[(r + g + 8) * 36 + ks * 8 + tg];
                a[mf][2] = As[(r + g    ) * 36 + ks * 8 + tg + 4];
                a[mf][3] = As[(r + g + 8) * 36 + ks * 8 + tg + 4];
            }
            #pragma unroll
            for (int nf = 0; nf < 8; nf++) {
                unsigned bb[2];
                int c = wn * 64 + nf * 8 + g;
                bb[0] = Bs[(ks * 8 + tg    ) * 136 + c];
                bb[1] = Bs[(ks * 8 + tg + 4) * 136 + c];
                mma8(acc[0][nf], a[0], bb);
                mma8(acc[1][nf], a[1], bb);
            }
        }
        __syncthreads();
        if (kt + 2 < nt) issue(kt + 2, kt & 1);
        else asm volatile("cp.async.commit_group;");
    }

    #pragma unroll
    for (int mf = 0; mf < 2; mf++)
        #pragma unroll
        for (int nf = 0; nf < 8; nf++) {
            int row = bm + wm * 32 + mf * 16 + g;
            int col = bn + wn * 64 + nf * 8 + 2 * tg;
            float c0 = acc[mf][nf][0], c1 = acc[mf][nf][1];
            float c2 = acc[mf][nf][2], c3 = acc[mf][nf][3];
            if (ROPE) {
                if (col < 2 * EMB) {
                    int d = col & 63;
                    float freq = exp2f((float)d * -0.2076205059304601f); // 10000^(-d/64)
                    int s0 = row & (SEQ - 1);
                    int s1 = (row + 8) & (SEQ - 1);
                    float sn0, cs0, sn1, cs1;
                    sincosf((float)s0 * freq, &sn0, &cs0);
                    sincosf((float)s1 * freq, &sn1, &cs1);
                    float n0 = c0 * cs0 - c1 * sn0, n1 = c0 * sn0 + c1 * cs0;
                    float n2 = c2 * cs1 - c3 * sn1, n3 = c2 * sn1 + c3 * cs1;
                    c0 = n0; c1 = n1; c2 = n2; c3 = n3;
                }
                c0 = __uint_as_float(f2tf(c0)); c1 = __uint_as_float(f2tf(c1));
                c2 = __uint_as_float(f2tf(c2)); c3 = __uint_as_float(f2tf(c3));
            }
            *(float2*)(C + (size_t)row * N + col)       = make_float2(c0, c1);
            *(float2*)(C + (size_t)(row + 8) * N + col) = make_float2(c2, c3);
        }
}

// ---------------------------------------------------------------------------
// Flash attention, tf32 mma.sync.
// 256 threads (8 warps), q-tile 128 rows (warp w: rows 16w..16w+15), kv tile 64.
// Q fragments register-resident (tf32 bits, *1/8 exact). P stays in registers:
// V rows are sigma-permuted at store (orig row 8a+u -> 8a + (u&1 ? u/2+4 : u/2))
// so the S-accumulator fragment layout IS the PV A-fragment layout
// (pa = {s0, s2, s1, s3}; verified correct in round 7).
// 2 barriers per kv-tile. Inactive warps skip compute but hit all barriers.
// ---------------------------------------------------------------------------
__global__ __launch_bounds__(256, 2) void attn_mma(
    const float* __restrict__ qkv, float* __restrict__ out)
{
    __shared__ unsigned Kp[64][68];
    __shared__ unsigned Vp[64][72];

    const int tid  = threadIdx.x;
    const int lane = tid & 31;
    const int warp = tid >> 5;
    const int g    = lane >> 2;
    const int tg   = lane & 3;
    const int qt   = gridDim.x - 1 - blockIdx.x;   // heavy tiles first
    const int h    = blockIdx.y;
    const int b    = blockIdx.z;
    const int q0   = qt * 128;
    const int m0   = warp * 16;

    const float* qb = qkv + (size_t)b * SEQ * QKV3 + h * HD;
    const float* kb = qb + EMB;
    const float* vb = qb + 2 * EMB;

    // Q fragments (tf32 bits already; *0.125f exact power of two)
    unsigned qa[8][4];
    #pragma unroll
    for (int ks = 0; ks < 8; ks++) {
        const float* r0p = qb + (size_t)(q0 + m0 + g) * QKV3 + ks * 8 + tg;
        const float* r1p = r0p + (size_t)8 * QKV3;
        qa[ks][0] = __float_as_uint(0.125f * r0p[0]);
        qa[ks][1] = __float_as_uint(0.125f * r1p[0]);
        qa[ks][2] = __float_as_uint(0.125f * r0p[4]);
        qa[ks][3] = __float_as_uint(0.125f * r1p[4]);
    }

    float m_r[2] = {-1e30f, -1e30f};
    float l_r[2] = {0.0f, 0.0f};
    float o[8][4];
    #pragma unroll
    for (int nf = 0; nf < 8; nf++)
        #pragma unroll
        for (int i = 0; i < 4; i++) o[nf][i] = 0.0f;

    const int last = 2 * qt + 1;
    for (int kt = 0; kt <= last; kt++) {
        const int k0 = kt * 64;
        __syncthreads();   // previous iteration's smem reads done

        // Load K (natural rows) and V (sigma-permuted rows); raw tf32 bits.
        #pragma unroll
        for (int t = 0; t < 4; t++) {
            int idx = tid + t * 256;
            int r = idx >> 4, c4 = (idx & 15) * 4;
            *(uint4*)&Kp[r][c4] = *(const uint4*)(kb + (size_t)(k0 + r) * QKV3 + c4);
            int u = r & 7, a = r >> 3;
            int rp = 8 * a + ((u & 1) ? (u >> 1) + 4 : (u >> 1));
            *(uint4*)&Vp[rp][c4] = *(const uint4*)(vb + (size_t)(k0 + r) * QKV3 + c4);
        }
        __syncthreads();

        const bool active = (k0 <= q0 + m0 + 15);
        if (!active) continue;

        // S = (Q/8) @ K^T
        float s[8][4];
        #pragma unroll
        for (int nf = 0; nf < 8; nf++)
            #pragma unroll
            for (int i = 0; i < 4; i++) s[nf][i] = 0.0f;

        #pragma unroll
        for (int ks = 0; ks < 8; ks++) {
            #pragma unroll
            for (int nf = 0; nf < 8; nf++) {
                unsigned bb[2];
                bb[0] = Kp[nf * 8 + g][ks * 8 + tg];
                bb[1] = Kp[nf * 8 + g][ks * 8 + tg + 4];
                mma8(s[nf], qa[ks], bb);
            }
        }

        // Causal mask (tiles overlapping this warp's diagonal)
        if (k0 + 63 > q0 + m0) {
            int r0 = q0 + m0 + g, r1 = r0 + 8;
            #pragma unroll
            for (int nf = 0; nf < 8; nf++) {
                int col = k0 + nf * 8 + 2 * tg;
                if (col     > r0) s[nf][0] = -1e9f;
                if (col + 1 > r0) s[nf][1] = -1e9f;
                if (col     > r1) s[nf][2] = -1e9f;
                if (col + 1 > r1) s[nf][3] = -1e9f;
            }
        }

        // Online softmax (row i=0 -> g, i=1 -> g+8; reduce across 4 tg lanes)
        #pragma unroll
        for (int i = 0; i < 2; i++) {
            float mx = -1e30f;
            #pragma unroll
            for (int nf = 0; nf < 8; nf++)
                mx = fmaxf(mx, fmaxf(s[nf][2 * i], s[nf][2 * i + 1]));
            mx = fmaxf(mx, __shfl_xor_sync(0xffffffffu, mx, 1));
            mx = fmaxf(mx, __shfl_xor_sync(0xffffffffu, mx, 2));
            float mn   = fmaxf(m_r[i], mx);
            float corr = __expf(m_r[i] - mn);
            m_r[i] = mn;
            float rs = 0.0f;
            #pragma unroll
            for (int nf = 0; nf < 8; nf++) {
                float p0 = __expf(s[nf][2 * i]     - mn);
                float p1 = __expf(s[nf][2 * i + 1] - mn);
                s[nf][2 * i] = p0; s[nf][2 * i + 1] = p1;
                rs += p0 + p1;
            }
            rs += __shfl_xor_sync(0xffffffffu, rs, 1);
            rs += __shfl_xor_sync(0xffffffffu, rs, 2);
            l_r[i] = l_r[i] * corr + rs;
            #pragma unroll
            for (int nf = 0; nf < 8; nf++) {
                o[nf][2 * i]     *= corr;
                o[nf][2 * i + 1] *= corr;
            }
        }

        // O += P @ V  (P in registers, V sigma-permuted)
        #pragma unroll
        for (int ks = 0; ks < 8; ks++) {
            unsigned pa[4] = {f2tf(s[ks][0]), f2tf(s[ks][2]),
                              f2tf(s[ks][1]), f2tf(s[ks][3])};
            #pragma unroll
            for (int nf = 0; nf < 8; nf++) {
                unsigned bb[2];
                bb[0] = Vp[ks * 8 + tg    ][nf * 8 + g];
                bb[1] = Vp[ks * 8 + tg + 4][nf * 8 + g];
                mma8(o[nf], pa, bb);
            }
        }
    }

    // Epilogue: normalize, store tf32 bits to att buffer [b*s, h*d]
    #pragma unroll
    for (int i = 0; i < 2; i++) {
        float inv = 1.0f / l_r[i];
        int row = q0 + m0 + g + 8 * i;
        float* op = out + ((size_t)b * SEQ + row) * EMB + h * HD;
        #pragma unroll
        for (int nf = 0; nf < 8; nf++) {
            int col = nf * 8 + 2 * tg;
            *(float2*)(op + col) = make_float2(
                __uint_as_float(f2tf(o[nf][2 * i]     * inv)),
                __uint_as_float(f2tf(o[nf][2 * i + 1] * inv)));
        }
    }
}

// ---------------------------------------------------------------------------
extern "C" void kernel_launch(void* const* d_in, const int* in_sizes, int n_in,
                              void* d_out, int out_size)
{
    const float* x    = (const float*)d_in[0];
    const float* Wqkv = (const float*)d_in[1];
    const float* Wout = (const float*)d_in[2];
    float* out        = (float*)d_out;

    float *qkv = nullptr, *att = nullptr;
    unsigned *xt = nullptr, *wqt = nullptr, *wot = nullptr;
    cudaGetSymbolAddress((void**)&qkv, g_qkv);
    cudaGetSymbolAddress((void**)&att, g_att);
    cudaGetSymbolAddress((void**)&xt,  g_xt);
    cudaGetSymbolAddress((void**)&wqt, g_wqt);
    cudaGetSymbolAddress((void**)&wot, g_wot);

    static bool attr_set = false;
    if (!attr_set) {
        cudaFuncSetAttribute(gemm_tc<1>,
            cudaFuncAttributeMaxDynamicSharedMemorySize, GEMM_SMEM_BYTES);
        cudaFuncSetAttribute(gemm_tc<0>,
            cudaFuncAttributeMaxDynamicSharedMemorySize, GEMM_SMEM_BYTES);
        attr_set = true;
    }

    // 0) pre-convert operands to tf32 bit patterns
    {
        int n4x = MROWS * EMB / 4;
        int n4q = EMB * QKV3 / 4;
        int n4o = EMB * EMB / 4;
        cvt_tf32_kernel<<<(n4x + 255) / 256, 256>>>((const float4*)x,    (uint4*)xt,  n4x);
        cvt_tf32_kernel<<<(n4q + 255) / 256, 256>>>((const float4*)Wqkv, (uint4*)wqt, n4q);
        cvt_tf32_kernel<<<(n4o + 255) / 256, 256>>>((const float4*)Wout, (uint4*)wot, n4o);
    }
    // 1) QKV projection + fused RoPE (tf32-bit output)
    {
        dim3 grid(QKV3 / 128, MROWS / 128);
        gemm_tc<1><<<grid, 256, GEMM_SMEM_BYTES>>>(xt, wqt, qkv, MROWS, QKV3, EMB);
    }
    // 2) Causal flash attention (tf32-bit in/out), 128-row q tiles
    {
        dim3 grid(SEQ / 128, NH, BATCH);
        attn_mma<<<grid, 256>>>(qkv, att);
    }
    // 3) Output projection (fp32 output)
    {
        dim3 grid(EMB / 128, MROWS / 128);
        gemm_tc<0><<<grid, 256, GEMM_SMEM_BYTES>>>((const unsigned*)att, wot, out,
                                                   MROWS, EMB, EMB);
    }
}